// round 8
// baseline (speedup 1.0000x reference)
#include <cuda_runtime.h>
#include <math.h>

#define B   128
#define T   256
#define H   512
#define H4  2048
#define V   128
#define LW  32
#define SOS 1
#define BH  (B*H)      // 65536
#define NBLK 128
#define NTHR 256

// ---------------- device scratch (static) ----------------
__device__ float g_enc0[(size_t)B*T*2*H];   // [b][t][dir*H+u]
__device__ float g_enc1[(size_t)B*T*2*H];   // [b][t][dir*H+u]
__device__ float g_h0[2*2*BH];              // [parity][dir][b][u]
__device__ float g_h1[2*2*BH];
__device__ float g_c0[2*BH];                // [dir][b][u]
__device__ float g_c1[2*BH];
__device__ float g_dech[2*2*BH];            // [parity][l][b][u]
__device__ float g_decc[2*BH];              // [l][b][u]
__device__ float g_query[B*2*H];
__device__ float g_ctx[B*2*H];
__device__ float g_comb[B*H];
__device__ int   g_tok[B];

__device__ unsigned g_cnt = 0;
__device__ volatile unsigned g_gen = 0;

// packed dual-fp32 FMA (Blackwell f32x2 path; bitwise == 2x scalar fmaf)
#define FMA2(c, a, b) \
    asm("fma.rn.f32x2 %0, %1, %2, %0;" : "+l"(c) : "l"(a), "l"(b))

// ---------------- software grid barrier ----------------
__device__ __forceinline__ void gbar(unsigned &gen)
{
    __syncthreads();
    if (threadIdx.x == 0) {
        __threadfence();
        unsigned t = atomicAdd(&g_cnt, 1u);
        if (t == NBLK - 1u) {
            atomicExch(&g_cnt, 0u);
            __threadfence();
            g_gen = gen + 1u;
        } else {
            while (g_gen == gen) {}
            __threadfence();
        }
    }
    __syncthreads();
    gen++;
}

// ---------------- Shared-memory union layout (floats) ----------------
// [0      .. 2112)  As[2][8][132]   gate-GEMM A tiles (128 rows, padded)
// [2112   .. 3200)  Bs[2][8][68]    gate-GEMM B tiles (32 cols duplicated)
// [3200   .. 7424)  GS  [128][33]   gate tile / attention / logits scratch
// mm_plain uses [0 .. 8192) (different phases, never concurrent)
#define U_SIZE 8448

// ---------------- FFMA2 gate GEMM ----------------
// acc[4][2] u64 pairs: pair mp covers rows {ty*8+2mp, +1}, col n of {2tx, 2tx+1}
// C-tile: 128(M) x 32(N = 4 gates x 8 u at u0). K multiple of 8, K/8 even.
__device__ __forceinline__ void mm_pair(
    unsigned long long acc[4][2],
    const float* __restrict__ A, long lda, const int* __restrict__ idx,
    const float* __restrict__ W, int u0, int K, float* __restrict__ U)
{
    float (*As)[8][132] = (float (*)[8][132])U;
    float (*Bs)[8][68]  = (float (*)[8][68])(U + 2112);
    const int tid = threadIdx.x;
    const int ty = tid >> 4, tx = tid & 15;
    // A loader: 1 float4 per chunk (row lm, k-seg lk)
    const int lm = tid >> 1;
    const int lk = (tid & 1) * 4;
    long arow = idx ? (long)idx[lm] : (long)lm;
    const float* Ab = A + arow * lda + lk;
    // B loader: 1 float per chunk (k-row bk, tile col bn)
    const int bk = tid >> 5;
    const int bn = tid & 31;
    const float* Wb = W + (long)bk * H4 + (bn >> 3) * H + u0 + (bn & 7);

    const int NC = K >> 3;
    float4 av = *(const float4*)(Ab);
    float  bv = *Wb;
    As[0][lk+0][lm] = av.x; As[0][lk+1][lm] = av.y;
    As[0][lk+2][lm] = av.z; As[0][lk+3][lm] = av.w;
    Bs[0][bk][2*bn] = bv;   Bs[0][bk][2*bn+1] = bv;
    __syncthreads();
    int cur = 0;
    for (int ch = 0; ch < NC; ch++) {
        if (ch + 1 < NC) {
            av = *(const float4*)(Ab + (ch + 1) * 8);
            bv = *(Wb + (long)(ch + 1) * 8 * H4);
        }
        #pragma unroll
        for (int k = 0; k < 8; k++) {
            ulonglong2 a01 = *(const ulonglong2*)&As[cur][k][ty*8];
            ulonglong2 a23 = *(const ulonglong2*)&As[cur][k][ty*8 + 4];
            ulonglong2 bb  = *(const ulonglong2*)&Bs[cur][k][tx*4];
            FMA2(acc[0][0], a01.x, bb.x); FMA2(acc[0][1], a01.x, bb.y);
            FMA2(acc[1][0], a01.y, bb.x); FMA2(acc[1][1], a01.y, bb.y);
            FMA2(acc[2][0], a23.x, bb.x); FMA2(acc[2][1], a23.x, bb.y);
            FMA2(acc[3][0], a23.y, bb.x); FMA2(acc[3][1], a23.y, bb.y);
        }
        if (ch + 1 < NC) {
            int nxt = cur ^ 1;
            As[nxt][lk+0][lm] = av.x; As[nxt][lk+1][lm] = av.y;
            As[nxt][lk+2][lm] = av.z; As[nxt][lk+3][lm] = av.w;
            Bs[nxt][bk][2*bn] = bv;   Bs[nxt][bk][2*bn+1] = bv;
            __syncthreads();
            cur = nxt;
        }
    }
    // NC even at every call site -> next call's first STS hits buffer 0 race-free
}

// store gate accumulators into GS[128][33]
__device__ __forceinline__ void store_gates(unsigned long long acc[4][2], float* U)
{
    float (*GS)[33] = (float (*)[33])(U + 3200);
    const int ty = threadIdx.x >> 4, tx = threadIdx.x & 15;
    #pragma unroll
    for (int mp = 0; mp < 4; mp++) {
        #pragma unroll
        for (int n = 0; n < 2; n++) {
            float2 f = *(float2*)&acc[mp][n];
            GS[ty*8 + 2*mp + 0][2*tx + n] = f.x;
            GS[ty*8 + 2*mp + 1][2*tx + n] = f.y;
        }
    }
}

// ---------------- old-style double-buffered plain GEMM (query/comb) -------
__device__ __forceinline__ void mm_plain(
    float acc[4][4],
    const float* __restrict__ A, long lda, int m0,
    const float* __restrict__ W, int ldw, int K, int n0, float* sh)
{
    float (*As)[16][64] = (float (*)[16][64])sh;
    float (*Bs)[16][64] = (float (*)[16][64])(sh + 2048);
    const int tid = threadIdx.x;
    const int ty = tid >> 4, tx = tid & 15;
    const int am = tid >> 2, ak = (tid & 3) * 4;
    const float* Ab = A + (long)(m0 + am) * lda + ak;
    const int bk  = tid >> 4;
    const int btx = tid & 15;
    const float* Wb = W + (long)bk * ldw + n0 + btx * 4;

    const int NC = K >> 4;
    float4 av = *(const float4*)(Ab);
    float4 bv = *(const float4*)(Wb);
    As[0][ak+0][am] = av.x; As[0][ak+1][am] = av.y;
    As[0][ak+2][am] = av.z; As[0][ak+3][am] = av.w;
    *(float4*)&Bs[0][bk][btx*4] = bv;
    __syncthreads();
    int cur = 0;
    for (int ch = 0; ch < NC; ch++) {
        if (ch + 1 < NC) {
            av = *(const float4*)(Ab + (ch + 1) * 16);
            bv = *(const float4*)(Wb + (long)(ch + 1) * 16 * ldw);
        }
        const float (* __restrict__ Ac)[64] = As[cur];
        const float (* __restrict__ Bc)[64] = Bs[cur];
        #pragma unroll
        for (int k = 0; k < 16; k++) {
            float4 a = *(const float4*)&Ac[k][ty*4];
            float4 b = *(const float4*)&Bc[k][tx*4];
            float aa[4] = {a.x,a.y,a.z,a.w};
            float bb[4] = {b.x,b.y,b.z,b.w};
            #pragma unroll
            for (int i = 0; i < 4; i++)
                #pragma unroll
                for (int j = 0; j < 4; j++)
                    acc[i][j] = fmaf(aa[i], bb[j], acc[i][j]);
        }
        if (ch + 1 < NC) {
            int nxt = cur ^ 1;
            As[nxt][ak+0][am] = av.x; As[nxt][ak+1][am] = av.y;
            As[nxt][ak+2][am] = av.z; As[nxt][ak+3][am] = av.w;
            *(float4*)&Bs[nxt][bk][btx*4] = bv;
            __syncthreads();
            cur = nxt;
        }
    }
}

__device__ __forceinline__ float sigm(float v) { return 1.f/(1.f + expf(-v)); }

// ---------------- the single persistent kernel ----------------
__global__ void __launch_bounds__(NTHR, 1)
traj_kernel(const float* __restrict__ x,
            const float* __restrict__ w0ih, const float* __restrict__ w0hh, const float* __restrict__ b0,
            const float* __restrict__ w1ih, const float* __restrict__ w1hh, const float* __restrict__ b1,
            const float* __restrict__ dWih, const float* __restrict__ dWhh, const float* __restrict__ db,
            const float* __restrict__ emb,
            const float* __restrict__ Wq,  const float* __restrict__ bq,
            const float* __restrict__ Wc,  const float* __restrict__ bc,
            const float* __restrict__ Wf,  const float* __restrict__ bfv,
            float* __restrict__ out)
{
    __shared__ __align__(16) float U[U_SIZE];
    float (*GS)[33] = (float (*)[33])(U + 3200);
    float* GSf = U + 3200;

    const int blk = blockIdx.x;
    const int tid = threadIdx.x;
    unsigned gen = 0;

    // ---- init: zero states (parity 0) ----
    for (int i = blk*NTHR + tid; i < 2*BH; i += NBLK*NTHR) {
        g_h0[i] = 0.f; g_h1[i] = 0.f;
        g_c0[i] = 0.f; g_c1[i] = 0.f;
    }
    gbar(gen);

    // ---- encoder: per block (dir, u-tile of 8) ----
    {
        const int dir = blk >> 6;
        const int u0  = (blk & 63) * 8;
        for (int layer = 0; layer < 2; layer++) {
            const float* bias_d = (layer ? b1 : b0) + (long)dir*H4;
            const float* Wi     = w0ih + (long)dir*2*H4;
            float* cB = (layer ? g_c1 : g_c0) + (long)dir*BH;
            float* y  = layer ? g_enc1 : g_enc0;
            for (int tf = 0; tf < T; tf++) {
                const int t = dir ? (T - 1 - tf) : tf;
                const int po = (tf & 1) * 2 * BH;
                const int pn = ((tf + 1) & 1) * 2 * BH;
                unsigned long long acc[4][2] = {};
                if (layer == 0) {
                    mm_pair(acc, g_h0 + po + (long)dir*BH, H, nullptr,
                            w0hh + (long)dir*H*H4, u0, H, U);
                } else {
                    mm_pair(acc, g_enc0 + (long)t*2*H, (long)T*2*H, nullptr,
                            w1ih + (long)dir*(2*H)*H4, u0, 2*H, U);
                    mm_pair(acc, g_h1 + po + (long)dir*BH, H, nullptr,
                            w1hh + (long)dir*H*H4, u0, H, U);
                }
                store_gates(acc, U);
                __syncthreads();
                float* hN = (layer ? g_h1 : g_h0) + pn + (long)dir*BH;
                #pragma unroll
                for (int r = 0; r < 4; r++) {
                    int e = tid + r*NTHR;          // < 1024
                    int b = e >> 3, ui = e & 7;
                    int u = u0 + ui;
                    float gi = GS[b][ui]      + bias_d[u];
                    float gf = GS[b][8+ui]    + bias_d[512+u];
                    float gg = GS[b][16+ui]   + bias_d[1024+u];
                    float go = GS[b][24+ui]   + bias_d[1536+u];
                    if (layer == 0) {
                        float x0 = x[((long)b*T + t)*2 + 0];
                        float x1 = x[((long)b*T + t)*2 + 1];
                        gi += x0*Wi[u]        + x1*Wi[H4 + u];
                        gf += x0*Wi[512+u]    + x1*Wi[H4 + 512+u];
                        gg += x0*Wi[1024+u]   + x1*Wi[H4 + 1024+u];
                        go += x0*Wi[1536+u]   + x1*Wi[H4 + 1536+u];
                    }
                    long su = (long)b*H + u;
                    float cn = sigm(gf)*cB[su] + sigm(gi)*tanhf(gg);
                    float hn = sigm(go)*tanhf(cn);
                    cB[su] = cn;
                    hN[su] = hn;
                    y[((long)b*T + t)*(2*H) + dir*H + u] = hn;
                }
                gbar(gen);
            }
        }
    }

    // ---- decoder init ----
    for (int i = blk*NTHR + tid; i < BH; i += NBLK*NTHR) {
        g_dech[i]      = g_h0[i] + g_h0[BH + i];
        g_decc[i]      = g_c0[i] + g_c0[BH + i];
        g_dech[BH + i] = g_h1[i] + g_h1[BH + i];
        g_decc[BH + i] = g_c1[i] + g_c1[BH + i];
    }
    if (blk == 0 && tid < B) g_tok[tid] = SOS;
    gbar(gen);

    const int ty = tid >> 4, tx = tid & 15;

    // ---- decoder: 32 greedy steps ----
    for (int s = 0; s < LW; s++) {
        const int po = (s & 1) * 2 * BH;
        const int pn = ((s + 1) & 1) * 2 * BH;

        // LSTM layers (FFMA2 gate GEMM + fused update), 64 blocks active
        for (int l = 0; l < 2; l++) {
            if (blk < 64) {
                const int u0 = blk * 8;
                unsigned long long acc[4][2] = {};
                if (l == 0)
                    mm_pair(acc, emb, H, g_tok, dWih, u0, H, U);
                else
                    mm_pair(acc, g_dech + pn, H, nullptr, dWih + (long)H*H4, u0, H, U);
                mm_pair(acc, g_dech + po + (long)l*BH, H, nullptr,
                        dWhh + (long)l*H*H4, u0, H, U);
                store_gates(acc, U);
                __syncthreads();
                const float* bias_d = db + (long)l*H4;
                float* hN = g_dech + pn + (long)l*BH;
                float* cB = g_decc + (long)l*BH;
                #pragma unroll
                for (int r = 0; r < 4; r++) {
                    int e = tid + r*NTHR;
                    int b = e >> 3, ui = e & 7;
                    int u = u0 + ui;
                    float gi = GS[b][ui]      + bias_d[u];
                    float gf = GS[b][8+ui]    + bias_d[512+u];
                    float gg = GS[b][16+ui]   + bias_d[1024+u];
                    float go = GS[b][24+ui]   + bias_d[1536+u];
                    long su = (long)b*H + u;
                    float cn = sigm(gf)*cB[su] + sigm(gi)*tanhf(gg);
                    float hn = sigm(go)*tanhf(cn);
                    cB[su] = cn;
                    hN[su] = hn;
                }
            }
            gbar(gen);
        }

        // query = h1_new @ Wq + bq
        if (blk < 32) {
            const int m0 = (blk >> 4) * 64;
            const int n0 = (blk & 15) * 64;
            float acc[4][4] = {};
            mm_plain(acc, g_dech + pn + BH, H, m0, Wq, 2*H, H, n0, U);
            #pragma unroll
            for (int i = 0; i < 4; i++) {
                int m = m0 + ty*4 + i;
                #pragma unroll
                for (int j = 0; j < 4; j++) {
                    int n = n0 + tx*4 + j;
                    g_query[(long)m*(2*H) + n] = acc[i][j] + bq[n];
                }
            }
        }
        gbar(gen);

        // attention per batch (block = batch)
        {
            const int b = blk;
            float* qs  = GSf;            // [1024]
            float* sc  = GSf + 1024;     // [256]
            float* red = GSf + 1280;     // [256]
            for (int e = tid; e < 2*H; e += NTHR) qs[e] = g_query[(long)b*2*H + e];
            __syncthreads();
            const int warp = tid >> 5, lane = tid & 31;
            for (int tb = 0; tb < T; tb += 8) {
                int t = tb + warp;
                const float* row = g_enc1 + ((long)b*T + t)*(2*H);
                float p = 0.f;
                for (int e = lane; e < 2*H; e += 32) p = fmaf(row[e], qs[e], p);
                #pragma unroll
                for (int o = 16; o; o >>= 1) p += __shfl_xor_sync(0xffffffffu, p, o);
                if (lane == 0) sc[t] = p;
            }
            __syncthreads();
            float v = sc[tid];
            red[tid] = v; __syncthreads();
            for (int o = 128; o; o >>= 1) {
                if (tid < o) red[tid] = fmaxf(red[tid], red[tid + o]);
                __syncthreads();
            }
            float mx = red[0]; __syncthreads();
            float e = expf(v - mx);
            red[tid] = e; __syncthreads();
            for (int o = 128; o; o >>= 1) {
                if (tid < o) red[tid] += red[tid + o];
                __syncthreads();
            }
            float a = e / red[0];
            sc[tid] = a;
            out[786432 + ((long)b*T + tid)*LW + s] = a;
            __syncthreads();
            for (int ec = tid; ec < 2*H; ec += NTHR) {
                float accv = 0.f;
                const float* base = g_enc1 + ((long)b*T)*(2*H) + ec;
                for (int t = 0; t < T; t++) accv = fmaf(sc[t], base[(long)t*2*H], accv);
                g_ctx[(long)b*2*H + ec] = accv;
            }
        }
        gbar(gen);

        // combined = [h1 | ctx] @ Wc + bc
        if (blk < 16) {
            const int m0 = (blk >> 3) * 64;
            const int n0 = (blk & 7) * 64;
            float acc[4][4] = {};
            mm_plain(acc, g_dech + pn + BH, H, m0, Wc, H, H, n0, U);
            mm_plain(acc, g_ctx, 2*H, m0, Wc + (long)H*H, H, 2*H, n0, U);
            #pragma unroll
            for (int i = 0; i < 4; i++) {
                int m = m0 + ty*4 + i;
                #pragma unroll
                for (int j = 0; j < 4; j++) {
                    int n = n0 + tx*4 + j;
                    g_comb[(long)m*H + n] = acc[i][j] + bc[n];
                }
            }
        }
        gbar(gen);

        // logits + argmax (block = batch)
        {
            const int b = blk;
            float* cs = GSf;             // [512]
            float* sv = GSf + 512;       // [128]
            int*   si = (int*)(GSf + 640);
            for (int k = tid; k < H; k += NTHR) cs[k] = g_comb[(long)b*H + k];
            __syncthreads();
            if (tid < V) {
                float acc = bfv[tid];
                for (int k = 0; k < H; k++) acc = fmaf(cs[k], Wf[(long)k*V + tid], acc);
                out[((long)b*LW + s)*V + tid] = acc;
                sv[tid] = acc; si[tid] = tid;
            }
            __syncthreads();
            for (int o = 64; o; o >>= 1) {
                if (tid < o) {
                    float v2 = sv[tid + o]; int i2 = si[tid + o];
                    if (v2 > sv[tid] || (v2 == sv[tid] && i2 < si[tid])) {
                        sv[tid] = v2; si[tid] = i2;
                    }
                }
                __syncthreads();
            }
            if (tid == 0) g_tok[b] = si[0];
        }
        gbar(gen);
    }

    // ---- final states (parity 0 after 32 steps) ----
    for (int i = blk*NTHR + tid; i < 2*BH; i += NBLK*NTHR) {
        out[524288 + i] = g_dech[i];
        out[655360 + i] = g_decc[i];
    }
}

// ---------------- host launch: ONE graph node ----------------
extern "C" void kernel_launch(void* const* d_in, const int* in_sizes, int n_in,
                              void* d_out, int out_size)
{
    (void)in_sizes; (void)n_in; (void)out_size;
    traj_kernel<<<NBLK, NTHR>>>(
        (const float*)d_in[0],  (const float*)d_in[1],  (const float*)d_in[2],
        (const float*)d_in[3],  (const float*)d_in[4],  (const float*)d_in[5],
        (const float*)d_in[6],  (const float*)d_in[7],  (const float*)d_in[8],
        (const float*)d_in[9],  (const float*)d_in[10], (const float*)d_in[11],
        (const float*)d_in[12], (const float*)d_in[13], (const float*)d_in[14],
        (const float*)d_in[15], (const float*)d_in[16], (float*)d_out);
}

// round 11
// speedup vs baseline: 1.7493x; 1.7493x over previous
#include <cuda_runtime.h>
#include <math.h>

#define B   128
#define T   256
#define H   512
#define H4  2048
#define V   128
#define LW  32
#define SOS 1
#define BH  (B*H)      // 65536
#define NBLK 128
#define NTHR 512

// ---------------- device scratch (static) ----------------
__device__ float g_enc0[(size_t)B*T*2*H];   // [b][t][dir*H+u]
__device__ float g_enc1[(size_t)B*T*2*H];   // [b][t][dir*H+u]
__device__ float g_h0[2*2*BH];              // [parity][dir][b][u]
__device__ float g_h1[2*2*BH];
__device__ float g_c0[2*BH];                // [dir][b][u]
__device__ float g_c1[2*BH];
__device__ float g_dech[2*2*BH];            // [parity][l][b][u]
__device__ float g_decc[2*BH];              // [l][b][u]
__device__ float g_query[B*2*H];
__device__ float g_ctx[B*2*H];
__device__ float g_comb[B*H];
__device__ int   g_tok[B];

__device__ unsigned g_cnt = 0;
__device__ volatile unsigned g_gen = 0;

// ---------------- software grid barrier ----------------
__device__ __forceinline__ void gbar(unsigned &gen)
{
    __syncthreads();
    if (threadIdx.x == 0) {
        __threadfence();
        unsigned t = atomicAdd(&g_cnt, 1u);
        if (t == NBLK - 1u) {
            atomicExch(&g_cnt, 0u);
            __threadfence();
            g_gen = gen + 1u;
        } else {
            while (g_gen == gen) {}
            __threadfence();
        }
    }
    __syncthreads();
    gen++;
}

// ---------------- SMEM layout (floats), exactly 48 KB ----------------
// [0 .. 8192)   4 K-groups x (As[2][8][64] + Bs[2][8][64]) = 4 x 2048
// [8192..12288) GS[64][64]  gate tile / reduce / attention / logits scratch
#define SH_FLOATS 12288

// ---------------- 8x4-micro, 4-way-K-split, double-buffered GEMM ----------
// Block tile: 64(M) x 64(N). 512 threads = 4 K-groups x 128.
// Group gid handles K range [gid*K/4, (gid+1)*K/4), chunks of 8 K.
// Per thread: 32 outputs, rows my*8..+7, cols nx*4..+3 (partial sums).
// gateu0 >= 0: gate column mapping col(n) = (n>>4)*H + gateu0 + (n&15)
// gateu0 <  0: plain mapping col(n) = n0 + n
// REQUIRES: (K/4) % 16 == 0  (NC even -> buffer handoff race-free)
__device__ __forceinline__ void mm84(
    float acc[8][4],
    const float* __restrict__ A, long lda, const int* __restrict__ idx, int m0,
    const float* __restrict__ W, long ldw, int gateu0, int n0, int K,
    float* __restrict__ SH)
{
    const int tid = threadIdx.x;
    const int gid = tid >> 7;
    const int g   = tid & 127;
    float* as_ = SH + gid * 2048;
    float* bs_ = SH + gid * 2048 + 1024;

    const int Kq   = K >> 2;
    const int koff = gid * Kq;
    const int NC   = Kq >> 3;

    // A loader: row lrow (0..63), 4-float K-seg lseg
    const int lrow = g >> 1, lseg = (g & 1) * 4;
    long arow = idx ? (long)idx[m0 + lrow] : (long)(m0 + lrow);
    const float* Ab = A + arow * lda + koff + lseg;
    // B loader: K-row bk (0..7), 4-col seg bn4
    const int bk = g >> 4, bn4 = (g & 15) * 4;
    const int col = (gateu0 >= 0) ? ((bn4 >> 4) * H + gateu0 + (bn4 & 15))
                                  : (n0 + bn4);
    const float* Wb = W + (long)(koff + bk) * ldw + col;
    // compute mapping
    const int my = g >> 4;      // 0..7
    const int nx = g & 15;      // 0..15

    float4 av = *(const float4*)Ab;
    float4 bv = *(const float4*)Wb;
    as_[(lseg+0)*64 + lrow] = av.x;
    as_[(lseg+1)*64 + lrow] = av.y;
    as_[(lseg+2)*64 + lrow] = av.z;
    as_[(lseg+3)*64 + lrow] = av.w;
    *(float4*)(bs_ + bk*64 + bn4) = bv;
    __syncthreads();

    int cur = 0;
    for (int ch = 0; ch < NC; ch++) {
        if (ch + 1 < NC) {
            av = *(const float4*)(Ab + (ch + 1) * 8);
            bv = *(const float4*)(Wb + (long)(ch + 1) * 8 * ldw);
        }
        const float* ab = as_ + cur * 512;
        const float* bb = bs_ + cur * 512;
        #pragma unroll
        for (int k = 0; k < 8; k++) {
            float4 b4 = *(const float4*)(bb + k*64 + nx*4);
            float4 a0 = *(const float4*)(ab + k*64 + my*8);
            float4 a1 = *(const float4*)(ab + k*64 + my*8 + 4);
            float aa[8] = {a0.x,a0.y,a0.z,a0.w,a1.x,a1.y,a1.z,a1.w};
            float bbv[4] = {b4.x,b4.y,b4.z,b4.w};
            #pragma unroll
            for (int i = 0; i < 8; i++)
                #pragma unroll
                for (int j = 0; j < 4; j++)
                    acc[i][j] = fmaf(aa[i], bbv[j], acc[i][j]);
        }
        if (ch + 1 < NC) {
            int nxt = cur ^ 1;
            float* an = as_ + nxt * 512;
            float* bn_ = bs_ + nxt * 512;
            an[(lseg+0)*64 + lrow] = av.x;
            an[(lseg+1)*64 + lrow] = av.y;
            an[(lseg+2)*64 + lrow] = av.z;
            an[(lseg+3)*64 + lrow] = av.w;
            *(float4*)(bn_ + bk*64 + bn4) = bv;
            __syncthreads();
            cur = nxt;
        }
    }
}

// ---- sum the 4 K-group partials into GS[64][64] (order 3->2->1->0) ----
__device__ __forceinline__ void reduce_groups(float acc[8][4], float* __restrict__ GSf)
{
    float (*GS)[64] = (float (*)[64])GSf;
    const int tid = threadIdx.x;
    const int gid = tid >> 7, g = tid & 127;
    const int my = g >> 4, nx = g & 15;
    if (gid == 3) {
        #pragma unroll
        for (int i = 0; i < 8; i++)
            #pragma unroll
            for (int j = 0; j < 4; j++)
                GS[my*8+i][nx*4+j] = acc[i][j];
    }
    __syncthreads();
    if (gid == 2) {
        #pragma unroll
        for (int i = 0; i < 8; i++)
            #pragma unroll
            for (int j = 0; j < 4; j++)
                GS[my*8+i][nx*4+j] += acc[i][j];
    }
    __syncthreads();
    if (gid == 1) {
        #pragma unroll
        for (int i = 0; i < 8; i++)
            #pragma unroll
            for (int j = 0; j < 4; j++)
                GS[my*8+i][nx*4+j] += acc[i][j];
    }
    __syncthreads();
    if (gid == 0) {
        #pragma unroll
        for (int i = 0; i < 8; i++)
            #pragma unroll
            for (int j = 0; j < 4; j++)
                GS[my*8+i][nx*4+j] += acc[i][j];
    }
    __syncthreads();
}

__device__ __forceinline__ float sigm(float v) { return 1.f/(1.f + expf(-v)); }

// ---------------- the single persistent kernel ----------------
__global__ void __launch_bounds__(NTHR, 1)
traj_kernel(const float* __restrict__ x,
            const float* __restrict__ w0ih, const float* __restrict__ w0hh, const float* __restrict__ b0,
            const float* __restrict__ w1ih, const float* __restrict__ w1hh, const float* __restrict__ b1,
            const float* __restrict__ dWih, const float* __restrict__ dWhh, const float* __restrict__ db,
            const float* __restrict__ emb,
            const float* __restrict__ Wq,  const float* __restrict__ bq,
            const float* __restrict__ Wc,  const float* __restrict__ bc,
            const float* __restrict__ Wf,  const float* __restrict__ bfv,
            float* __restrict__ out)
{
    __shared__ __align__(16) float SH[SH_FLOATS];
    float* GSf = SH + 8192;
    float (*GS)[64] = (float (*)[64])GSf;

    const int blk = blockIdx.x;
    const int tid = threadIdx.x;
    unsigned gen = 0;

    // ---- init: zero states (parity 0) ----
    for (int i = blk*NTHR + tid; i < 2*BH; i += NBLK*NTHR) {
        g_h0[i] = 0.f; g_h1[i] = 0.f;
        g_c0[i] = 0.f; g_c1[i] = 0.f;
    }
    gbar(gen);

    // ---- encoder: per block (dir, m-half, u-tile of 16) ----
    {
        const int dir = blk >> 6;
        const int m0  = ((blk >> 5) & 1) * 64;
        const int u0  = (blk & 31) * 16;
        for (int layer = 0; layer < 2; layer++) {
            const float* bias_d = (layer ? b1 : b0) + (long)dir*H4;
            const float* Wi     = w0ih + (long)dir*2*H4;
            float* cB = (layer ? g_c1 : g_c0) + (long)dir*BH;
            float* y  = layer ? g_enc1 : g_enc0;
            for (int tf = 0; tf < T; tf++) {
                const int t = dir ? (T - 1 - tf) : tf;
                const int po = (tf & 1) * 2 * BH;
                const int pn = ((tf + 1) & 1) * 2 * BH;
                float acc[8][4] = {};
                if (layer == 0) {
                    mm84(acc, g_h0 + po + (long)dir*BH, H, nullptr, m0,
                         w0hh + (long)dir*H*H4, H4, u0, 0, H, SH);
                } else {
                    mm84(acc, g_enc0 + (long)t*2*H, (long)T*2*H, nullptr, m0,
                         w1ih + (long)dir*(2*H)*H4, H4, u0, 0, 2*H, SH);
                    mm84(acc, g_h1 + po + (long)dir*BH, H, nullptr, m0,
                         w1hh + (long)dir*H*H4, H4, u0, 0, H, SH);
                }
                reduce_groups(acc, GSf);
                // fused LSTM update for this block's (m, u) tile
                float* hN = (layer ? g_h1 : g_h0) + pn + (long)dir*BH;
                #pragma unroll
                for (int r = 0; r < 2; r++) {
                    int e = tid + r*NTHR;          // < 1024
                    int ml = e >> 4, ui = e & 15;
                    int b = m0 + ml, u = u0 + ui;
                    float gi = GS[ml][ui]      + bias_d[u];
                    float gf = GS[ml][16+ui]   + bias_d[512+u];
                    float gg = GS[ml][32+ui]   + bias_d[1024+u];
                    float go = GS[ml][48+ui]   + bias_d[1536+u];
                    if (layer == 0) {
                        float x0 = x[((long)b*T + t)*2 + 0];
                        float x1 = x[((long)b*T + t)*2 + 1];
                        gi += x0*Wi[u]        + x1*Wi[H4 + u];
                        gf += x0*Wi[512+u]    + x1*Wi[H4 + 512+u];
                        gg += x0*Wi[1024+u]   + x1*Wi[H4 + 1024+u];
                        go += x0*Wi[1536+u]   + x1*Wi[H4 + 1536+u];
                    }
                    long su = (long)b*H + u;
                    float cn = sigm(gf)*cB[su] + sigm(gi)*tanhf(gg);
                    float hn = sigm(go)*tanhf(cn);
                    cB[su] = cn;
                    hN[su] = hn;
                    y[((long)b*T + t)*(2*H) + dir*H + u] = hn;
                }
                gbar(gen);
            }
        }
    }

    // ---- decoder init ----
    for (int i = blk*NTHR + tid; i < BH; i += NBLK*NTHR) {
        g_dech[i]      = g_h0[i] + g_h0[BH + i];
        g_decc[i]      = g_c0[i] + g_c0[BH + i];
        g_dech[BH + i] = g_h1[i] + g_h1[BH + i];
        g_decc[BH + i] = g_c1[i] + g_c1[BH + i];
    }
    if (blk == 0 && tid < B) g_tok[tid] = SOS;
    gbar(gen);

    // ---- decoder: 32 greedy steps ----
    for (int s = 0; s < LW; s++) {
        const int po = (s & 1) * 2 * BH;
        const int pn = ((s + 1) & 1) * 2 * BH;

        // LSTM layers (gate GEMM + fused update), 64 blocks active
        for (int l = 0; l < 2; l++) {
            if (blk < 64) {
                const int m0 = (blk >> 5) * 64;
                const int u0 = (blk & 31) * 16;
                float acc[8][4] = {};
                if (l == 0)
                    mm84(acc, emb, H, g_tok, m0, dWih, H4, u0, 0, H, SH);
                else
                    mm84(acc, g_dech + pn, H, nullptr, m0,
                         dWih + (long)H*H4, H4, u0, 0, H, SH);
                mm84(acc, g_dech + po + (long)l*BH, H, nullptr, m0,
                     dWhh + (long)l*H*H4, H4, u0, 0, H, SH);
                reduce_groups(acc, GSf);
                const float* bias_d = db + (long)l*H4;
                float* hN = g_dech + pn + (long)l*BH;
                float* cB = g_decc + (long)l*BH;
                #pragma unroll
                for (int r = 0; r < 2; r++) {
                    int e = tid + r*NTHR;
                    int ml = e >> 4, ui = e & 15;
                    int u = u0 + ui;
                    float gi = GS[ml][ui]      + bias_d[u];
                    float gf = GS[ml][16+ui]   + bias_d[512+u];
                    float gg = GS[ml][32+ui]   + bias_d[1024+u];
                    float go = GS[ml][48+ui]   + bias_d[1536+u];
                    long su = (long)(m0 + ml)*H + u;
                    float cn = sigm(gf)*cB[su] + sigm(gi)*tanhf(gg);
                    float hn = sigm(go)*tanhf(cn);
                    cB[su] = cn;
                    hN[su] = hn;
                }
            }
            gbar(gen);
        }

        // query = h1_new @ Wq + bq   (32 blocks, 64x64 tiles)
        if (blk < 32) {
            const int m0 = (blk >> 4) * 64;
            const int n0 = (blk & 15) * 64;
            float acc[8][4] = {};
            mm84(acc, g_dech + pn + BH, H, nullptr, m0, Wq, 2*H, -1, n0, H, SH);
            reduce_groups(acc, GSf);
            #pragma unroll
            for (int r = 0; r < 8; r++) {
                int e = tid + r*NTHR;        // < 4096
                int mrow = e >> 6, ncol = e & 63;
                g_query[(long)(m0 + mrow)*(2*H) + n0 + ncol] =
                    GS[mrow][ncol] + bq[n0 + ncol];
            }
        }
        gbar(gen);

        // attention per batch (block = batch)
        {
            const int b = blk;
            float* qs  = GSf;            // [1024]
            float* sc  = GSf + 1024;     // [256]
            float* red = GSf + 1280;     // [512]
            for (int e = tid; e < 2*H; e += NTHR) qs[e] = g_query[(long)b*2*H + e];
            __syncthreads();
            const int warp = tid >> 5, lane = tid & 31;
            for (int tb = 0; tb < T; tb += 16) {
                int t = tb + warp;
                const float* row = g_enc1 + ((long)b*T + t)*(2*H);
                float p = 0.f;
                for (int e = lane; e < 2*H; e += 32) p = fmaf(row[e], qs[e], p);
                #pragma unroll
                for (int o = 16; o; o >>= 1) p += __shfl_xor_sync(0xffffffffu, p, o);
                if (lane == 0) sc[t] = p;
            }
            __syncthreads();
            float v = (tid < T) ? sc[tid] : -1e30f;
            red[tid] = v; __syncthreads();
            for (int o = 256; o; o >>= 1) {
                if (tid < o) red[tid] = fmaxf(red[tid], red[tid + o]);
                __syncthreads();
            }
            float mx = red[0]; __syncthreads();
            float e = expf(v - mx);
            red[tid] = (tid < T) ? e : 0.f; __syncthreads();
            for (int o = 256; o; o >>= 1) {
                if (tid < o) red[tid] += red[tid + o];
                __syncthreads();
            }
            if (tid < T) {
                float a = e / red[0];
                sc[tid] = a;
                out[786432 + ((long)b*T + tid)*LW + s] = a;
            }
            __syncthreads();
            for (int ec = tid; ec < 2*H; ec += NTHR) {
                float accv = 0.f;
                const float* base = g_enc1 + ((long)b*T)*(2*H) + ec;
                for (int t = 0; t < T; t++) accv = fmaf(sc[t], base[(long)t*2*H], accv);
                g_ctx[(long)b*2*H + ec] = accv;
            }
        }
        gbar(gen);

        // combined = [h1 | ctx] @ Wc + bc   (16 blocks)
        if (blk < 16) {
            const int m0 = (blk >> 3) * 64;
            const int n0 = (blk & 7) * 64;
            float acc[8][4] = {};
            mm84(acc, g_dech + pn + BH, H, nullptr, m0, Wc, H, -1, n0, H, SH);
            mm84(acc, g_ctx, 2*H, nullptr, m0, Wc + (long)H*H, H, -1, n0, 2*H, SH);
            reduce_groups(acc, GSf);
            #pragma unroll
            for (int r = 0; r < 8; r++) {
                int e = tid + r*NTHR;
                int mrow = e >> 6, ncol = e & 63;
                g_comb[(long)(m0 + mrow)*H + n0 + ncol] =
                    GS[mrow][ncol] + bc[n0 + ncol];
            }
        }
        gbar(gen);

        // logits + argmax (block = batch)
        {
            const int b = blk;
            float* cs = GSf;             // [512]
            float* sv = GSf + 512;       // [128]
            int*   si = (int*)(GSf + 640);
            for (int k = tid; k < H; k += NTHR) cs[k] = g_comb[(long)b*H + k];
            __syncthreads();
            if (tid < V) {
                float acc = bfv[tid];
                for (int k = 0; k < H; k++) acc = fmaf(cs[k], Wf[(long)k*V + tid], acc);
                out[((long)b*LW + s)*V + tid] = acc;
                sv[tid] = acc; si[tid] = tid;
            }
            __syncthreads();
            for (int o = 64; o; o >>= 1) {
                if (tid < o) {
                    float v2 = sv[tid + o]; int i2 = si[tid + o];
                    if (v2 > sv[tid] || (v2 == sv[tid] && i2 < si[tid])) {
                        sv[tid] = v2; si[tid] = i2;
                    }
                }
                __syncthreads();
            }
            if (tid == 0) g_tok[b] = si[0];
        }
        gbar(gen);
    }

    // ---- final states (parity 0 after 32 steps) ----
    for (int i = blk*NTHR + tid; i < 2*BH; i += NBLK*NTHR) {
        out[524288 + i] = g_dech[i];
        out[655360 + i] = g_decc[i];
    }
}

// ---------------- host launch: ONE graph node ----------------
extern "C" void kernel_launch(void* const* d_in, const int* in_sizes, int n_in,
                              void* d_out, int out_size)
{
    (void)in_sizes; (void)n_in; (void)out_size;
    traj_kernel<<<NBLK, NTHR>>>(
        (const float*)d_in[0],  (const float*)d_in[1],  (const float*)d_in[2],
        (const float*)d_in[3],  (const float*)d_in[4],  (const float*)d_in[5],
        (const float*)d_in[6],  (const float*)d_in[7],  (const float*)d_in[8],
        (const float*)d_in[9],  (const float*)d_in[10], (const float*)d_in[11],
        (const float*)d_in[12], (const float*)d_in[13], (const float*)d_in[14],
        (const float*)d_in[15], (const float*)d_in[16], (float*)d_out);
}

// round 12
// speedup vs baseline: 1.9185x; 1.0967x over previous
#include <cuda_runtime.h>
#include <math.h>

#define B   128
#define T   256
#define H   512
#define H4  2048
#define V   128
#define LW  32
#define SOS 1
#define BH  (B*H)      // 65536
#define NBLK 128
#define NTHR 512

// ---------------- device scratch (static) ----------------
__device__ float g_enc0[(size_t)B*T*2*H];   // [b][t][dir*H+u]
__device__ float g_enc1[(size_t)B*T*2*H];   // [b][t][dir*H+u]
__device__ float g_h0[2*2*BH];              // [parity][dir][b][u]
__device__ float g_h1[2*2*BH];
__device__ float g_c0[2*BH];                // [dir][b][u]
__device__ float g_c1[2*BH];
__device__ float g_dech[2*2*BH];            // [parity][l][b][u]
__device__ float g_decc[2*BH];              // [l][b][u]
__device__ float g_ctx[B*2*H];
__device__ float g_gpart[(size_t)B*H4];     // decoder input-side gate partial
__device__ float g_queryP[2][B*2*H];        // query K-split partials
__device__ float g_combP[3][B*H];           // combined K-split partials
__device__ int   g_tok[B];

__device__ unsigned g_cnt = 0;
__device__ volatile unsigned g_gen = 0;

// ---------------- software grid barrier ----------------
__device__ __forceinline__ void gbar(unsigned &gen)
{
    __syncthreads();
    if (threadIdx.x == 0) {
        __threadfence();
        unsigned t = atomicAdd(&g_cnt, 1u);
        if (t == NBLK - 1u) {
            atomicExch(&g_cnt, 0u);
            __threadfence();
            g_gen = gen + 1u;
        } else {
            while (g_gen == gen) {}
            __threadfence();
        }
    }
    __syncthreads();
    gen++;
}

// ---------------- SMEM layout (floats), exactly 48 KB ----------------
// [0 .. 8192)   4 K-groups x (As[2][8][64] + Bs[2][8][64]) = 4 x 2048
// [8192..12288) GS[64][64]  gate tile / reduce / attention / logits scratch
#define SH_FLOATS 12288

// ---------------- 8x4-micro, 4-way-K-split, double-buffered GEMM ----------
// Block tile: 64(M) x 64(N). 512 threads = 4 K-groups x 128.
// gateu0 >= 0: gate column mapping col(n) = (n>>4)*H + gateu0 + (n&15)
// gateu0 <  0: plain mapping col(n) = n0 + n
// REQUIRES: (K/4) % 16 == 0  (NC even -> buffer handoff race-free)
__device__ __forceinline__ void mm84(
    float acc[8][4],
    const float* __restrict__ A, long lda, const int* __restrict__ idx, int m0,
    const float* __restrict__ W, long ldw, int gateu0, int n0, int K,
    float* __restrict__ SH)
{
    const int tid = threadIdx.x;
    const int gid = tid >> 7;
    const int g   = tid & 127;
    float* as_ = SH + gid * 2048;
    float* bs_ = SH + gid * 2048 + 1024;

    const int Kq   = K >> 2;
    const int koff = gid * Kq;
    const int NC   = Kq >> 3;

    const int lrow = g >> 1, lseg = (g & 1) * 4;
    long arow = idx ? (long)idx[m0 + lrow] : (long)(m0 + lrow);
    const float* Ab = A + arow * lda + koff + lseg;
    const int bk = g >> 4, bn4 = (g & 15) * 4;
    const int col = (gateu0 >= 0) ? ((bn4 >> 4) * H + gateu0 + (bn4 & 15))
                                  : (n0 + bn4);
    const float* Wb = W + (long)(koff + bk) * ldw + col;
    const int my = g >> 4;      // 0..7
    const int nx = g & 15;      // 0..15

    float4 av = *(const float4*)Ab;
    float4 bv = *(const float4*)Wb;
    as_[(lseg+0)*64 + lrow] = av.x;
    as_[(lseg+1)*64 + lrow] = av.y;
    as_[(lseg+2)*64 + lrow] = av.z;
    as_[(lseg+3)*64 + lrow] = av.w;
    *(float4*)(bs_ + bk*64 + bn4) = bv;
    __syncthreads();

    int cur = 0;
    for (int ch = 0; ch < NC; ch++) {
        if (ch + 1 < NC) {
            av = *(const float4*)(Ab + (ch + 1) * 8);
            bv = *(const float4*)(Wb + (long)(ch + 1) * 8 * ldw);
        }
        const float* ab = as_ + cur * 512;
        const float* bb = bs_ + cur * 512;
        #pragma unroll
        for (int k = 0; k < 8; k++) {
            float4 b4 = *(const float4*)(bb + k*64 + nx*4);
            float4 a0 = *(const float4*)(ab + k*64 + my*8);
            float4 a1 = *(const float4*)(ab + k*64 + my*8 + 4);
            float aa[8] = {a0.x,a0.y,a0.z,a0.w,a1.x,a1.y,a1.z,a1.w};
            float bbv[4] = {b4.x,b4.y,b4.z,b4.w};
            #pragma unroll
            for (int i = 0; i < 8; i++)
                #pragma unroll
                for (int j = 0; j < 4; j++)
                    acc[i][j] = fmaf(aa[i], bbv[j], acc[i][j]);
        }
        if (ch + 1 < NC) {
            int nxt = cur ^ 1;
            float* an = as_ + nxt * 512;
            float* bn_ = bs_ + nxt * 512;
            an[(lseg+0)*64 + lrow] = av.x;
            an[(lseg+1)*64 + lrow] = av.y;
            an[(lseg+2)*64 + lrow] = av.z;
            an[(lseg+3)*64 + lrow] = av.w;
            *(float4*)(bn_ + bk*64 + bn4) = bv;
            __syncthreads();
            cur = nxt;
        }
    }
}

// ---- sum the 4 K-group partials into GS[64][64] (order 3->2->1->0) ----
__device__ __forceinline__ void reduce_groups(float acc[8][4], float* __restrict__ GSf)
{
    float (*GS)[64] = (float (*)[64])GSf;
    const int tid = threadIdx.x;
    const int gid = tid >> 7, g = tid & 127;
    const int my = g >> 4, nx = g & 15;
    if (gid == 3) {
        #pragma unroll
        for (int i = 0; i < 8; i++)
            #pragma unroll
            for (int j = 0; j < 4; j++)
                GS[my*8+i][nx*4+j] = acc[i][j];
    }
    __syncthreads();
    if (gid == 2) {
        #pragma unroll
        for (int i = 0; i < 8; i++)
            #pragma unroll
            for (int j = 0; j < 4; j++)
                GS[my*8+i][nx*4+j] += acc[i][j];
    }
    __syncthreads();
    if (gid == 1) {
        #pragma unroll
        for (int i = 0; i < 8; i++)
            #pragma unroll
            for (int j = 0; j < 4; j++)
                GS[my*8+i][nx*4+j] += acc[i][j];
    }
    __syncthreads();
    if (gid == 0) {
        #pragma unroll
        for (int i = 0; i < 8; i++)
            #pragma unroll
            for (int j = 0; j < 4; j++)
                GS[my*8+i][nx*4+j] += acc[i][j];
    }
    __syncthreads();
}

__device__ __forceinline__ float sigm(float v) { return 1.f/(1.f + expf(-v)); }

// ---------------- the single persistent kernel ----------------
__global__ void __launch_bounds__(NTHR, 1)
traj_kernel(const float* __restrict__ x,
            const float* __restrict__ w0ih, const float* __restrict__ w0hh, const float* __restrict__ b0,
            const float* __restrict__ w1ih, const float* __restrict__ w1hh, const float* __restrict__ b1,
            const float* __restrict__ dWih, const float* __restrict__ dWhh, const float* __restrict__ db,
            const float* __restrict__ emb,
            const float* __restrict__ Wq,  const float* __restrict__ bq,
            const float* __restrict__ Wc,  const float* __restrict__ bc,
            const float* __restrict__ Wf,  const float* __restrict__ bfv,
            float* __restrict__ out)
{
    __shared__ __align__(16) float SH[SH_FLOATS];
    float* GSf = SH + 8192;
    float (*GS)[64] = (float (*)[64])GSf;

    const int blk = blockIdx.x;
    const int tid = threadIdx.x;
    unsigned gen = 0;

    // ---- init: zero states (parity 0) ----
    for (int i = blk*NTHR + tid; i < 2*BH; i += NBLK*NTHR) {
        g_h0[i] = 0.f; g_h1[i] = 0.f;
        g_c0[i] = 0.f; g_c1[i] = 0.f;
    }
    gbar(gen);

    // ---- encoder: per block (dir, m-half, u-tile of 16) — UNCHANGED ----
    {
        const int dir = blk >> 6;
        const int m0  = ((blk >> 5) & 1) * 64;
        const int u0  = (blk & 31) * 16;
        for (int layer = 0; layer < 2; layer++) {
            const float* bias_d = (layer ? b1 : b0) + (long)dir*H4;
            const float* Wi     = w0ih + (long)dir*2*H4;
            float* cB = (layer ? g_c1 : g_c0) + (long)dir*BH;
            float* y  = layer ? g_enc1 : g_enc0;
            for (int tf = 0; tf < T; tf++) {
                const int t = dir ? (T - 1 - tf) : tf;
                const int po = (tf & 1) * 2 * BH;
                const int pn = ((tf + 1) & 1) * 2 * BH;
                float acc[8][4] = {};
                if (layer == 0) {
                    mm84(acc, g_h0 + po + (long)dir*BH, H, nullptr, m0,
                         w0hh + (long)dir*H*H4, H4, u0, 0, H, SH);
                } else {
                    mm84(acc, g_enc0 + (long)t*2*H, (long)T*2*H, nullptr, m0,
                         w1ih + (long)dir*(2*H)*H4, H4, u0, 0, 2*H, SH);
                    mm84(acc, g_h1 + po + (long)dir*BH, H, nullptr, m0,
                         w1hh + (long)dir*H*H4, H4, u0, 0, H, SH);
                }
                reduce_groups(acc, GSf);
                float* hN = (layer ? g_h1 : g_h0) + pn + (long)dir*BH;
                #pragma unroll
                for (int r = 0; r < 2; r++) {
                    int e = tid + r*NTHR;          // < 1024
                    int ml = e >> 4, ui = e & 15;
                    int b = m0 + ml, u = u0 + ui;
                    float gi = GS[ml][ui]      + bias_d[u];
                    float gf = GS[ml][16+ui]   + bias_d[512+u];
                    float gg = GS[ml][32+ui]   + bias_d[1024+u];
                    float go = GS[ml][48+ui]   + bias_d[1536+u];
                    if (layer == 0) {
                        float x0 = x[((long)b*T + t)*2 + 0];
                        float x1 = x[((long)b*T + t)*2 + 1];
                        gi += x0*Wi[u]        + x1*Wi[H4 + u];
                        gf += x0*Wi[512+u]    + x1*Wi[H4 + 512+u];
                        gg += x0*Wi[1024+u]   + x1*Wi[H4 + 1024+u];
                        go += x0*Wi[1536+u]   + x1*Wi[H4 + 1536+u];
                    }
                    long su = (long)b*H + u;
                    float cn = sigm(gf)*cB[su] + sigm(gi)*tanhf(gg);
                    float hn = sigm(go)*tanhf(cn);
                    cB[su] = cn;
                    hN[su] = hn;
                    y[((long)b*T + t)*(2*H) + dir*H + u] = hn;
                }
                gbar(gen);
            }
        }
    }

    // ---- decoder init ----
    for (int i = blk*NTHR + tid; i < BH; i += NBLK*NTHR) {
        g_dech[i]      = g_h0[i] + g_h0[BH + i];
        g_decc[i]      = g_c0[i] + g_c0[BH + i];
        g_dech[BH + i] = g_h1[i] + g_h1[BH + i];
        g_decc[BH + i] = g_c1[i] + g_c1[BH + i];
    }
    if (blk == 0 && tid < B) g_tok[tid] = SOS;
    gbar(gen);

    // ---- decoder: 32 greedy steps ----
    for (int s = 0; s < LW; s++) {
        const int po = (s & 1) * 2 * BH;
        const int pn = ((s + 1) & 1) * 2 * BH;

        // LSTM layers: ALL 128 blocks = {w: input/hidden} x {m-half} x {32 u-tiles}
        for (int l = 0; l < 2; l++) {
            const int w  = blk >> 6;
            const int m0 = ((blk >> 5) & 1) * 64;
            const int u0 = (blk & 31) * 16;
            float acc[8][4] = {};
            if (w == 0) {
                if (l == 0)
                    mm84(acc, emb, H, g_tok, m0, dWih, H4, u0, 0, H, SH);
                else
                    mm84(acc, g_dech + pn, H, nullptr, m0,
                         dWih + (long)H*H4, H4, u0, 0, H, SH);
            } else {
                mm84(acc, g_dech + po + (long)l*BH, H, nullptr, m0,
                     dWhh + (long)l*H*H4, H4, u0, 0, H, SH);
            }
            reduce_groups(acc, GSf);
            if (w == 0) {
                // write input-side partial to global
                #pragma unroll
                for (int r = 0; r < 8; r++) {
                    int e = tid + r*NTHR;       // < 4096
                    int mrow = e >> 6, ncol = e & 63;
                    int col = (ncol >> 4)*H + u0 + (ncol & 15);
                    g_gpart[(long)(m0 + mrow)*H4 + col] = GS[mrow][ncol];
                }
            }
            gbar(gen);
            if (w == 1) {
                // hidden-side tile still in GS; add partial + bias, update state
                const float* bias_d = db + (long)l*H4;
                float* hN = g_dech + pn + (long)l*BH;
                float* cB = g_decc + (long)l*BH;
                #pragma unroll
                for (int r = 0; r < 2; r++) {
                    int e = tid + r*NTHR;       // < 1024
                    int ml = e >> 4, ui = e & 15;
                    int u = u0 + ui, m = m0 + ml;
                    const float* gp = g_gpart + (long)m*H4;
                    float gi = GS[ml][ui]      + gp[u]      + bias_d[u];
                    float gf = GS[ml][16+ui]   + gp[512+u]  + bias_d[512+u];
                    float gg = GS[ml][32+ui]   + gp[1024+u] + bias_d[1024+u];
                    float go = GS[ml][48+ui]   + gp[1536+u] + bias_d[1536+u];
                    long su = (long)m*H + u;
                    float cn = sigm(gf)*cB[su] + sigm(gi)*tanhf(gg);
                    float hn = sigm(go)*tanhf(cn);
                    cB[su] = cn;
                    hN[su] = hn;
                }
            }
            gbar(gen);
        }

        // query partials: 64 blocks = 2 K-parts x 32 tiles
        if (blk < 64) {
            const int part = blk >> 5;
            const int q  = blk & 31;
            const int m0 = (q >> 4) * 64;
            const int n0 = (q & 15) * 64;
            float acc[8][4] = {};
            mm84(acc, g_dech + pn + BH + part*256, H, nullptr, m0,
                 Wq + (long)(part*256)*(2*H), 2*H, -1, n0, 256, SH);
            reduce_groups(acc, GSf);
            #pragma unroll
            for (int r = 0; r < 8; r++) {
                int e = tid + r*NTHR;
                int mrow = e >> 6, ncol = e & 63;
                g_queryP[part][(long)(m0 + mrow)*(2*H) + n0 + ncol] = GS[mrow][ncol];
            }
        }
        gbar(gen);

        // attention per batch (block = batch)
        {
            const int b = blk;
            float* qs  = GSf;            // [1024]
            float* sc  = GSf + 1024;     // [256]
            float* red = GSf + 1280;     // [512]
            for (int e = tid; e < 2*H; e += NTHR)
                qs[e] = g_queryP[0][(long)b*2*H + e] + g_queryP[1][(long)b*2*H + e] + bq[e];
            __syncthreads();
            const int warp = tid >> 5, lane = tid & 31;
            for (int tb = 0; tb < T; tb += 16) {
                int t = tb + warp;
                const float* row = g_enc1 + ((long)b*T + t)*(2*H);
                float p = 0.f;
                for (int e = lane; e < 2*H; e += 32) p = fmaf(row[e], qs[e], p);
                #pragma unroll
                for (int o = 16; o; o >>= 1) p += __shfl_xor_sync(0xffffffffu, p, o);
                if (lane == 0) sc[t] = p;
            }
            __syncthreads();
            float v = (tid < T) ? sc[tid] : -1e30f;
            red[tid] = v; __syncthreads();
            for (int o = 256; o; o >>= 1) {
                if (tid < o) red[tid] = fmaxf(red[tid], red[tid + o]);
                __syncthreads();
            }
            float mx = red[0]; __syncthreads();
            float e = expf(v - mx);
            red[tid] = (tid < T) ? e : 0.f; __syncthreads();
            for (int o = 256; o; o >>= 1) {
                if (tid < o) red[tid] += red[tid + o];
                __syncthreads();
            }
            if (tid < T) {
                float a = e / red[0];
                sc[tid] = a;
                out[786432 + ((long)b*T + tid)*LW + s] = a;
            }
            __syncthreads();
            for (int ec = tid; ec < 2*H; ec += NTHR) {
                float accv = 0.f;
                const float* base = g_enc1 + ((long)b*T)*(2*H) + ec;
                for (int t = 0; t < T; t++) accv = fmaf(sc[t], base[(long)t*2*H], accv);
                g_ctx[(long)b*2*H + ec] = accv;
            }
        }
        gbar(gen);

        // combined partials: 48 blocks = 3 K-parts x 16 tiles
        if (blk < 48) {
            const int part = blk >> 4;
            const int q  = blk & 15;
            const int m0 = (q >> 3) * 64;
            const int n0 = (q & 7) * 64;
            float acc[8][4] = {};
            if (part == 0)
                mm84(acc, g_dech + pn + BH, H, nullptr, m0, Wc, H, -1, n0, 512, SH);
            else if (part == 1)
                mm84(acc, g_ctx, 2*H, nullptr, m0, Wc + (long)512*H, H, -1, n0, 512, SH);
            else
                mm84(acc, g_ctx + 512, 2*H, nullptr, m0, Wc + (long)1024*H, H, -1, n0, 512, SH);
            reduce_groups(acc, GSf);
            #pragma unroll
            for (int r = 0; r < 8; r++) {
                int e = tid + r*NTHR;
                int mrow = e >> 6, ncol = e & 63;
                g_combP[part][(long)(m0 + mrow)*H + n0 + ncol] = GS[mrow][ncol];
            }
        }
        gbar(gen);

        // logits + argmax (block = batch)
        {
            const int b = blk;
            float* cs = GSf;             // [512]
            float* sv = GSf + 512;       // [128]
            int*   si = (int*)(GSf + 640);
            for (int k = tid; k < H; k += NTHR)
                cs[k] = g_combP[0][(long)b*H + k] + g_combP[1][(long)b*H + k]
                      + g_combP[2][(long)b*H + k] + bc[k];
            __syncthreads();
            if (tid < V) {
                float acc = bfv[tid];
                for (int k = 0; k < H; k++) acc = fmaf(cs[k], Wf[(long)k*V + tid], acc);
                out[((long)b*LW + s)*V + tid] = acc;
                sv[tid] = acc; si[tid] = tid;
            }
            __syncthreads();
            for (int o = 64; o; o >>= 1) {
                if (tid < o) {
                    float v2 = sv[tid + o]; int i2 = si[tid + o];
                    if (v2 > sv[tid] || (v2 == sv[tid] && i2 < si[tid])) {
                        sv[tid] = v2; si[tid] = i2;
                    }
                }
                __syncthreads();
            }
            if (tid == 0) g_tok[b] = si[0];
        }
        gbar(gen);
    }

    // ---- final states (parity 0 after 32 steps) ----
    for (int i = blk*NTHR + tid; i < 2*BH; i += NBLK*NTHR) {
        out[524288 + i] = g_dech[i];
        out[655360 + i] = g_decc[i];
    }
}

// ---------------- host launch: ONE graph node ----------------
extern "C" void kernel_launch(void* const* d_in, const int* in_sizes, int n_in,
                              void* d_out, int out_size)
{
    (void)in_sizes; (void)n_in; (void)out_size;
    traj_kernel<<<NBLK, NTHR>>>(
        (const float*)d_in[0],  (const float*)d_in[1],  (const float*)d_in[2],
        (const float*)d_in[3],  (const float*)d_in[4],  (const float*)d_in[5],
        (const float*)d_in[6],  (const float*)d_in[7],  (const float*)d_in[8],
        (const float*)d_in[9],  (const float*)d_in[10], (const float*)d_in[11],
        (const float*)d_in[12], (const float*)d_in[13], (const float*)d_in[14],
        (const float*)d_in[15], (const float*)d_in[16], (float*)d_out);
}

// round 15
// speedup vs baseline: 1.9214x; 1.0015x over previous
#include <cuda_runtime.h>
#include <math.h>

#define B   128
#define T   256
#define H   512
#define H4  2048
#define V   128
#define LW  32
#define SOS 1
#define BH  (B*H)      // 65536
#define NBLK 128
#define NTHR 512

// ---------------- device scratch (static) ----------------
__device__ float g_enc0[(size_t)B*T*2*H];   // [b][t][dir*H+u]
__device__ float g_enc1[(size_t)B*T*2*H];   // [b][t][dir*H+u]
__device__ float g_h0[2*2*BH];              // [parity][dir][b][u]
__device__ float g_h1[2*2*BH];
__device__ float g_c0[2*BH];                // [dir][b][u]
__device__ float g_c1[2*BH];
__device__ float g_dech[2*2*BH];            // [parity][l][b][u]
__device__ float g_decc[2*BH];              // [l][b][u]
__device__ float g_ctx[B*2*H];
__device__ float g_gpart[(size_t)B*H4];     // decoder input-side gate partial
__device__ float g_queryP[2][B*2*H];        // query K-split partials
__device__ float g_combP[3][B*H];           // combined K-split partials
__device__ int   g_tok[B];

__device__ unsigned g_cnt = 0;
__device__ volatile unsigned g_gen = 0;

// ---------------- software grid barrier ----------------
__device__ __forceinline__ void gbar(unsigned &gen)
{
    __syncthreads();
    if (threadIdx.x == 0) {
        __threadfence();
        unsigned t = atomicAdd(&g_cnt, 1u);
        if (t == NBLK - 1u) {
            atomicExch(&g_cnt, 0u);
            __threadfence();
            g_gen = gen + 1u;
        } else {
            while (g_gen == gen) {}
            __threadfence();
        }
    }
    __syncthreads();
    gen++;
}

// ---------------- SMEM layout (floats), exactly 48 KB ----------------
// [0 .. 8192)   4 K-groups x (As[2][8][64] + Bs[2][8][64]) = 4 x 2048
// [8192..12288) GS[64][64]  gate tile / reduce / attention / logits scratch
#define SH_FLOATS 12288

// ---------------- 8x4-micro, 4-way-K-split, double-buffered GEMM ----------
// Block tile: 64(M) x 64(N). 512 threads = 4 K-groups x 128.
// gateu0 >= 0: gate column mapping col(n) = (n>>4)*H + gateu0 + (n&15)
// gateu0 <  0: plain mapping col(n) = n0 + n
// REQUIRES: (K/4) % 16 == 0  (NC even -> buffer handoff race-free)
__device__ __forceinline__ void mm84(
    float acc[8][4],
    const float* __restrict__ A, long lda, const int* __restrict__ idx, int m0,
    const float* __restrict__ W, long ldw, int gateu0, int n0, int K,
    float* __restrict__ SH)
{
    const int tid = threadIdx.x;
    const int gid = tid >> 7;
    const int g   = tid & 127;
    float* as_ = SH + gid * 2048;
    float* bs_ = SH + gid * 2048 + 1024;

    const int Kq   = K >> 2;
    const int koff = gid * Kq;
    const int NC   = Kq >> 3;

    const int lrow = g >> 1, lseg = (g & 1) * 4;
    long arow = idx ? (long)idx[m0 + lrow] : (long)(m0 + lrow);
    const float* Ab = A + arow * lda + koff + lseg;
    const int bk = g >> 4, bn4 = (g & 15) * 4;
    const int col = (gateu0 >= 0) ? ((bn4 >> 4) * H + gateu0 + (bn4 & 15))
                                  : (n0 + bn4);
    const float* Wb = W + (long)(koff + bk) * ldw + col;
    const int my = g >> 4;      // 0..7
    const int nx = g & 15;      // 0..15

    float4 av = *(const float4*)Ab;
    float4 bv = *(const float4*)Wb;
    as_[(lseg+0)*64 + lrow] = av.x;
    as_[(lseg+1)*64 + lrow] = av.y;
    as_[(lseg+2)*64 + lrow] = av.z;
    as_[(lseg+3)*64 + lrow] = av.w;
    *(float4*)(bs_ + bk*64 + bn4) = bv;
    __syncthreads();

    int cur = 0;
    for (int ch = 0; ch < NC; ch++) {
        if (ch + 1 < NC) {
            av = *(const float4*)(Ab + (ch + 1) * 8);
            bv = *(const float4*)(Wb + (long)(ch + 1) * 8 * ldw);
        }
        const float* ab = as_ + cur * 512;
        const float* bb = bs_ + cur * 512;
        #pragma unroll
        for (int k = 0; k < 8; k++) {
            float4 b4 = *(const float4*)(bb + k*64 + nx*4);
            float4 a0 = *(const float4*)(ab + k*64 + my*8);
            float4 a1 = *(const float4*)(ab + k*64 + my*8 + 4);
            float aa[8] = {a0.x,a0.y,a0.z,a0.w,a1.x,a1.y,a1.z,a1.w};
            float bbv[4] = {b4.x,b4.y,b4.z,b4.w};
            #pragma unroll
            for (int i = 0; i < 8; i++)
                #pragma unroll
                for (int j = 0; j < 4; j++)
                    acc[i][j] = fmaf(aa[i], bbv[j], acc[i][j]);
        }
        if (ch + 1 < NC) {
            int nxt = cur ^ 1;
            float* an = as_ + nxt * 512;
            float* bn_ = bs_ + nxt * 512;
            an[(lseg+0)*64 + lrow] = av.x;
            an[(lseg+1)*64 + lrow] = av.y;
            an[(lseg+2)*64 + lrow] = av.z;
            an[(lseg+3)*64 + lrow] = av.w;
            *(float4*)(bn_ + bk*64 + bn4) = bv;
            __syncthreads();
            cur = nxt;
        }
    }
}

// ---- sum the 4 K-group partials into GS[64][64] (order 3->2->1->0) ----
__device__ __forceinline__ void reduce_groups(float acc[8][4], float* __restrict__ GSf)
{
    float (*GS)[64] = (float (*)[64])GSf;
    const int tid = threadIdx.x;
    const int gid = tid >> 7, g = tid & 127;
    const int my = g >> 4, nx = g & 15;
    if (gid == 3) {
        #pragma unroll
        for (int i = 0; i < 8; i++)
            #pragma unroll
            for (int j = 0; j < 4; j++)
                GS[my*8+i][nx*4+j] = acc[i][j];
    }
    __syncthreads();
    if (gid == 2) {
        #pragma unroll
        for (int i = 0; i < 8; i++)
            #pragma unroll
            for (int j = 0; j < 4; j++)
                GS[my*8+i][nx*4+j] += acc[i][j];
    }
    __syncthreads();
    if (gid == 1) {
        #pragma unroll
        for (int i = 0; i < 8; i++)
            #pragma unroll
            for (int j = 0; j < 4; j++)
                GS[my*8+i][nx*4+j] += acc[i][j];
    }
    __syncthreads();
    if (gid == 0) {
        #pragma unroll
        for (int i = 0; i < 8; i++)
            #pragma unroll
            for (int j = 0; j < 4; j++)
                GS[my*8+i][nx*4+j] += acc[i][j];
    }
    __syncthreads();
}

__device__ __forceinline__ float sigm(float v) { return 1.f/(1.f + expf(-v)); }

// ---------------- the single persistent kernel ----------------
__global__ void __launch_bounds__(NTHR, 1)
traj_kernel(const float* __restrict__ x,
            const float* __restrict__ w0ih, const float* __restrict__ w0hh, const float* __restrict__ b0,
            const float* __restrict__ w1ih, const float* __restrict__ w1hh, const float* __restrict__ b1,
            const float* __restrict__ dWih, const float* __restrict__ dWhh, const float* __restrict__ db,
            const float* __restrict__ emb,
            const float* __restrict__ Wq,  const float* __restrict__ bq,
            const float* __restrict__ Wc,  const float* __restrict__ bc,
            const float* __restrict__ Wf,  const float* __restrict__ bfv,
            float* __restrict__ out)
{
    __shared__ __align__(16) float SH[SH_FLOATS];
    float* GSf = SH + 8192;
    float (*GS)[64] = (float (*)[64])GSf;

    const int blk = blockIdx.x;
    const int tid = threadIdx.x;
    unsigned gen = 0;

    // ---- init: zero states (parity 0) ----
    for (int i = blk*NTHR + tid; i < 2*BH; i += NBLK*NTHR) {
        g_h0[i] = 0.f; g_h1[i] = 0.f;
        g_c0[i] = 0.f; g_c1[i] = 0.f;
    }
    gbar(gen);

    // ---- encoder: per block (dir, m-half, u-tile of 16) — UNCHANGED ----
    {
        const int dir = blk >> 6;
        const int m0  = ((blk >> 5) & 1) * 64;
        const int u0  = (blk & 31) * 16;
        for (int layer = 0; layer < 2; layer++) {
            const float* bias_d = (layer ? b1 : b0) + (long)dir*H4;
            const float* Wi     = w0ih + (long)dir*2*H4;
            float* cB = (layer ? g_c1 : g_c0) + (long)dir*BH;
            float* y  = layer ? g_enc1 : g_enc0;
            for (int tf = 0; tf < T; tf++) {
                const int t = dir ? (T - 1 - tf) : tf;
                const int po = (tf & 1) * 2 * BH;
                const int pn = ((tf + 1) & 1) * 2 * BH;
                float acc[8][4] = {};
                if (layer == 0) {
                    mm84(acc, g_h0 + po + (long)dir*BH, H, nullptr, m0,
                         w0hh + (long)dir*H*H4, H4, u0, 0, H, SH);
                } else {
                    mm84(acc, g_enc0 + (long)t*2*H, (long)T*2*H, nullptr, m0,
                         w1ih + (long)dir*(2*H)*H4, H4, u0, 0, 2*H, SH);
                    mm84(acc, g_h1 + po + (long)dir*BH, H, nullptr, m0,
                         w1hh + (long)dir*H*H4, H4, u0, 0, H, SH);
                }
                reduce_groups(acc, GSf);
                float* hN = (layer ? g_h1 : g_h0) + pn + (long)dir*BH;
                #pragma unroll
                for (int r = 0; r < 2; r++) {
                    int e = tid + r*NTHR;          // < 1024
                    int ml = e >> 4, ui = e & 15;
                    int b = m0 + ml, u = u0 + ui;
                    float gi = GS[ml][ui]      + bias_d[u];
                    float gf = GS[ml][16+ui]   + bias_d[512+u];
                    float gg = GS[ml][32+ui]   + bias_d[1024+u];
                    float go = GS[ml][48+ui]   + bias_d[1536+u];
                    if (layer == 0) {
                        float x0 = x[((long)b*T + t)*2 + 0];
                        float x1 = x[((long)b*T + t)*2 + 1];
                        gi += x0*Wi[u]        + x1*Wi[H4 + u];
                        gf += x0*Wi[512+u]    + x1*Wi[H4 + 512+u];
                        gg += x0*Wi[1024+u]   + x1*Wi[H4 + 1024+u];
                        go += x0*Wi[1536+u]   + x1*Wi[H4 + 1536+u];
                    }
                    long su = (long)b*H + u;
                    float cn = sigm(gf)*cB[su] + sigm(gi)*tanhf(gg);
                    float hn = sigm(go)*tanhf(cn);
                    cB[su] = cn;
                    hN[su] = hn;
                    y[((long)b*T + t)*(2*H) + dir*H + u] = hn;
                }
                gbar(gen);
            }
        }
    }

    // ---- decoder init ----
    for (int i = blk*NTHR + tid; i < BH; i += NBLK*NTHR) {
        g_dech[i]      = g_h0[i] + g_h0[BH + i];
        g_decc[i]      = g_c0[i] + g_c0[BH + i];
        g_dech[BH + i] = g_h1[i] + g_h1[BH + i];
        g_decc[BH + i] = g_c1[i] + g_c1[BH + i];
    }
    if (blk == 0 && tid < B) g_tok[tid] = SOS;
    gbar(gen);

    // ---- decoder: 32 greedy steps ----
    for (int s = 0; s < LW; s++) {
        const int po = (s & 1) * 2 * BH;
        const int pn = ((s + 1) & 1) * 2 * BH;

        // LSTM layers: ALL 128 blocks = {w: input/hidden} x {m-half} x {32 u-tiles}
        for (int l = 0; l < 2; l++) {
            const int w  = blk >> 6;
            const int m0 = ((blk >> 5) & 1) * 64;
            const int u0 = (blk & 31) * 16;
            float acc[8][4] = {};
            if (w == 0) {
                if (l == 0)
                    mm84(acc, emb, H, g_tok, m0, dWih, H4, u0, 0, H, SH);
                else
                    mm84(acc, g_dech + pn, H, nullptr, m0,
                         dWih + (long)H*H4, H4, u0, 0, H, SH);
            } else {
                mm84(acc, g_dech + po + (long)l*BH, H, nullptr, m0,
                     dWhh + (long)l*H*H4, H4, u0, 0, H, SH);
            }
            reduce_groups(acc, GSf);
            if (w == 0) {
                // write input-side partial to global
                #pragma unroll
                for (int r = 0; r < 8; r++) {
                    int e = tid + r*NTHR;       // < 4096
                    int mrow = e >> 6, ncol = e & 63;
                    int col = (ncol >> 4)*H + u0 + (ncol & 15);
                    g_gpart[(long)(m0 + mrow)*H4 + col] = GS[mrow][ncol];
                }
            }
            gbar(gen);
            if (w == 1) {
                // hidden-side tile still in GS; add partial + bias, update state
                const float* bias_d = db + (long)l*H4;
                float* hN = g_dech + pn + (long)l*BH;
                float* cB = g_decc + (long)l*BH;
                #pragma unroll
                for (int r = 0; r < 2; r++) {
                    int e = tid + r*NTHR;       // < 1024
                    int ml = e >> 4, ui = e & 15;
                    int u = u0 + ui, m = m0 + ml;
                    const float* gp = g_gpart + (long)m*H4;
                    float gi = GS[ml][ui]      + gp[u]      + bias_d[u];
                    float gf = GS[ml][16+ui]   + gp[512+u]  + bias_d[512+u];
                    float gg = GS[ml][32+ui]   + gp[1024+u] + bias_d[1024+u];
                    float go = GS[ml][48+ui]   + gp[1536+u] + bias_d[1536+u];
                    long su = (long)m*H + u;
                    float cn = sigm(gf)*cB[su] + sigm(gi)*tanhf(gg);
                    float hn = sigm(go)*tanhf(cn);
                    cB[su] = cn;
                    hN[su] = hn;
                }
            }
            gbar(gen);
        }

        // query partials: 64 blocks = 2 K-parts x 32 tiles
        if (blk < 64) {
            const int part = blk >> 5;
            const int q  = blk & 31;
            const int m0 = (q >> 4) * 64;
            const int n0 = (q & 15) * 64;
            float acc[8][4] = {};
            mm84(acc, g_dech + pn + BH + part*256, H, nullptr, m0,
                 Wq + (long)(part*256)*(2*H), 2*H, -1, n0, 256, SH);
            reduce_groups(acc, GSf);
            #pragma unroll
            for (int r = 0; r < 8; r++) {
                int e = tid + r*NTHR;
                int mrow = e >> 6, ncol = e & 63;
                g_queryP[part][(long)(m0 + mrow)*(2*H) + n0 + ncol] = GS[mrow][ncol];
            }
        }
        gbar(gen);

        // attention per batch (block = batch)
        {
            const int b = blk;
            float* qs  = GSf;            // [1024]
            float* sc  = GSf + 1024;     // [256]
            float* red = GSf + 1280;     // [512]
            for (int e = tid; e < 2*H; e += NTHR)
                qs[e] = g_queryP[0][(long)b*2*H + e] + g_queryP[1][(long)b*2*H + e] + bq[e];
            __syncthreads();
            const int warp = tid >> 5, lane = tid & 31;
            for (int tb = 0; tb < T; tb += 16) {
                int t = tb + warp;
                const float* row = g_enc1 + ((long)b*T + t)*(2*H);
                float p = 0.f;
                for (int e = lane; e < 2*H; e += 32) p = fmaf(row[e], qs[e], p);
                #pragma unroll
                for (int o = 16; o; o >>= 1) p += __shfl_xor_sync(0xffffffffu, p, o);
                if (lane == 0) sc[t] = p;
            }
            __syncthreads();
            float v = (tid < T) ? sc[tid] : -1e30f;
            red[tid] = v; __syncthreads();
            for (int o = 256; o; o >>= 1) {
                if (tid < o) red[tid] = fmaxf(red[tid], red[tid + o]);
                __syncthreads();
            }
            float mx = red[0]; __syncthreads();
            float e = expf(v - mx);
            red[tid] = (tid < T) ? e : 0.f; __syncthreads();
            for (int o = 256; o; o >>= 1) {
                if (tid < o) red[tid] += red[tid + o];
                __syncthreads();
            }
            if (tid < T) {
                float a = e / red[0];
                sc[tid] = a;
                out[786432 + ((long)b*T + tid)*LW + s] = a;
            }
            __syncthreads();
            for (int ec = tid; ec < 2*H; ec += NTHR) {
                float accv = 0.f;
                const float* base = g_enc1 + ((long)b*T)*(2*H) + ec;
                for (int t = 0; t < T; t++) accv = fmaf(sc[t], base[(long)t*2*H], accv);
                g_ctx[(long)b*2*H + ec] = accv;
            }
        }
        gbar(gen);

        // combined partials: 48 blocks = 3 K-parts x 16 tiles
        if (blk < 48) {
            const int part = blk >> 4;
            const int q  = blk & 15;
            const int m0 = (q >> 3) * 64;
            const int n0 = (q & 7) * 64;
            float acc[8][4] = {};
            if (part == 0)
                mm84(acc, g_dech + pn + BH, H, nullptr, m0, Wc, H, -1, n0, 512, SH);
            else if (part == 1)
                mm84(acc, g_ctx, 2*H, nullptr, m0, Wc + (long)512*H, H, -1, n0, 512, SH);
            else
                mm84(acc, g_ctx + 512, 2*H, nullptr, m0, Wc + (long)1024*H, H, -1, n0, 512, SH);
            reduce_groups(acc, GSf);
            #pragma unroll
            for (int r = 0; r < 8; r++) {
                int e = tid + r*NTHR;
                int mrow = e >> 6, ncol = e & 63;
                g_combP[part][(long)(m0 + mrow)*H + n0 + ncol] = GS[mrow][ncol];
            }
        }
        gbar(gen);

        // logits + argmax (block = batch)
        {
            const int b = blk;
            float* cs = GSf;             // [512]
            float* sv = GSf + 512;       // [128]
            int*   si = (int*)(GSf + 640);
            for (int k = tid; k < H; k += NTHR)
                cs[k] = g_combP[0][(long)b*H + k] + g_combP[1][(long)b*H + k]
                      + g_combP[2][(long)b*H + k] + bc[k];
            __syncthreads();
            if (tid < V) {
                float acc = bfv[tid];
                for (int k = 0; k < H; k++) acc = fmaf(cs[k], Wf[(long)k*V + tid], acc);
                out[((long)b*LW + s)*V + tid] = acc;
                sv[tid] = acc; si[tid] = tid;
            }
            __syncthreads();
            for (int o = 64; o; o >>= 1) {
                if (tid < o) {
                    float v2 = sv[tid + o]; int i2 = si[tid + o];
                    if (v2 > sv[tid] || (v2 == sv[tid] && i2 < si[tid])) {
                        sv[tid] = v2; si[tid] = i2;
                    }
                }
                __syncthreads();
            }
            if (tid == 0) g_tok[b] = si[0];
        }
        gbar(gen);
    }

    // ---- final states (parity 0 after 32 steps) ----
    for (int i = blk*NTHR + tid; i < 2*BH; i += NBLK*NTHR) {
        out[524288 + i] = g_dech[i];
        out[655360 + i] = g_decc[i];
    }
}

// ---------------- host launch: ONE graph node ----------------
extern "C" void kernel_launch(void* const* d_in, const int* in_sizes, int n_in,
                              void* d_out, int out_size)
{
    (void)in_sizes; (void)n_in; (void)out_size;
    traj_kernel<<<NBLK, NTHR>>>(
        (const float*)d_in[0],  (const float*)d_in[1],  (const float*)d_in[2],
        (const float*)d_in[3],  (const float*)d_in[4],  (const float*)d_in[5],
        (const float*)d_in[6],  (const float*)d_in[7],  (const float*)d_in[8],
        (const float*)d_in[9],  (const float*)d_in[10], (const float*)d_in[11],
        (const float*)d_in[12], (const float*)d_in[13], (const float*)d_in[14],
        (const float*)d_in[15], (const float*)d_in[16], (float*)d_out);
}